// round 3
// baseline (speedup 1.0000x reference)
#include <cuda_runtime.h>
#include <cstdint>

#define N_NODES 50000
#define N_EDGES 800000
#define D 128
#define VOCAB 30000
#define BATCH 1024
#define CTX_LEN 50

// ---------------- scratch (no allocations allowed) ----------------
__device__ float g_agg[(size_t)N_NODES * D];
__device__ float g_z[(size_t)N_NODES * D];
__device__ float g_h[(size_t)N_NODES * D];
__device__ float g_in256[BATCH * 256];
__device__ float g_qin[BATCH * 256];
__device__ float g_q1[BATCH * 256];
__device__ float g_stats[256];

// ---------------- utility: zero float4s ----------------
__global__ void zero_kernel(float4* __restrict__ p, int n4) {
    int i = blockIdx.x * blockDim.x + threadIdx.x;
    int stride = gridDim.x * blockDim.x;
    for (; i < n4; i += stride) p[i] = make_float4(0.f, 0.f, 0.f, 0.f);
}

// ---------------- sparse aggregation: agg[row] += norm * h[col] ----------------
// warp per edge; lane handles one float4 of the 128-wide row.
// Next-edge index prefetch overlaps the (row,col,norm) loads with the red issue.
__global__ void scatter_kernel(const int* __restrict__ rows, const int* __restrict__ cols,
                               const float* __restrict__ norm, const float* __restrict__ h,
                               float* __restrict__ agg, int nE) {
    int lane = threadIdx.x & 31;
    int warp = blockIdx.x * (blockDim.x >> 5) + (threadIdx.x >> 5);
    int nwarps = gridDim.x * (blockDim.x >> 5);
    int e = warp;
    if (e >= nE) return;
    int r = rows[e];
    int c = cols[e];
    float w = norm[e];
    for (; e < nE; ) {
        int en = e + nwarps;
        int rn = 0, cn = 0;
        float wn = 0.f;
        if (en < nE) {                     // prefetch next edge header
            rn = rows[en];
            cn = cols[en];
            wn = norm[en];
        }
        float4 v = *((const float4*)(h + (size_t)c * D) + lane);
        float* dst = agg + (size_t)r * D + lane * 4;
        asm volatile("red.global.add.v4.f32 [%0], {%1,%2,%3,%4};"
                     :: "l"(dst), "f"(v.x * w), "f"(v.y * w), "f"(v.z * w), "f"(v.w * w)
                     : "memory");
        e = en; r = rn; c = cn; w = wn;
    }
}

// ---------------- generic GEMM: out[M,N] = act(A[M,K] @ W[N,K]^T + bias) ----------------
// block tile 64x128, 256 threads, thread microtile 8 rows x 4 cols (cols strided by 32).
// Optional fused per-column sum/sumsq accumulation (for BN) into stats[256].
#define SBK 129
#define GEMM_SMEM ((64 * 128 + 128 * SBK) * 4)

__global__ void __launch_bounds__(256, 2)
gemm_kernel(const float* __restrict__ A, const float* __restrict__ W,
            const float* __restrict__ bias, float* __restrict__ out,
            int M, int N, int K, int ldout, int do_relu, float* __restrict__ stats) {
    extern __shared__ float sm[];
    float* sA = sm;              // [64][128]
    float* sB = sm + 64 * 128;   // [128][SBK]
    int tid = threadIdx.x;
    int lane = tid & 31, wid = tid >> 5;
    int bm = blockIdx.x * 64;
    int bn = blockIdx.y * 128;

    float acc[8][4];
#pragma unroll
    for (int i = 0; i < 8; i++)
#pragma unroll
        for (int c = 0; c < 4; c++) acc[i][c] = 0.f;

    int rg = wid * 8;
    for (int k0 = 0; k0 < K; k0 += 128) {
        __syncthreads();
        // A tile: 64 rows x 128 k (float4, coalesced; zero-pad rows >= M)
        for (int i = tid; i < 64 * 32; i += 256) {
            int r = i >> 5, c4 = i & 31;
            int gr = bm + r;
            float4 v = make_float4(0.f, 0.f, 0.f, 0.f);
            if (gr < M) v = *(const float4*)(A + (size_t)gr * K + k0 + c4 * 4);
            *(float4*)(sA + r * 128 + c4 * 4) = v;
        }
        // B tile: natural [n][k] layout, stride 129 for conflict-free strided-col reads
        for (int i = tid; i < 128 * 32; i += 256) {
            int n = i >> 5, k4 = i & 31;
            float4 v = *(const float4*)(W + (size_t)(bn + n) * K + k0 + k4 * 4);
            float* p = sB + n * SBK + k4 * 4;
            p[0] = v.x; p[1] = v.y; p[2] = v.z; p[3] = v.w;
        }
        __syncthreads();
#pragma unroll 4
        for (int k = 0; k < 128; k++) {
            float b0 = sB[(lane)      * SBK + k];
            float b1 = sB[(lane + 32) * SBK + k];
            float b2 = sB[(lane + 64) * SBK + k];
            float b3 = sB[(lane + 96) * SBK + k];
#pragma unroll
            for (int i = 0; i < 8; i++) {
                float a = sA[(rg + i) * 128 + k];
                acc[i][0] = fmaf(a, b0, acc[i][0]);
                acc[i][1] = fmaf(a, b1, acc[i][1]);
                acc[i][2] = fmaf(a, b2, acc[i][2]);
                acc[i][3] = fmaf(a, b3, acc[i][3]);
            }
        }
    }

    // epilogue
    float bv[4];
#pragma unroll
    for (int c = 0; c < 4; c++) bv[c] = bias ? bias[bn + lane + 32 * c] : 0.f;
    float psum[4] = {0.f, 0.f, 0.f, 0.f}, psq[4] = {0.f, 0.f, 0.f, 0.f};
#pragma unroll
    for (int i = 0; i < 8; i++) {
        int gr = bm + rg + i;
        if (gr < M) {
#pragma unroll
            for (int c = 0; c < 4; c++) {
                float v = acc[i][c] + bv[c];
                if (do_relu) v = fmaxf(v, 0.f);
                out[(size_t)gr * ldout + bn + lane + 32 * c] = v;
                psum[c] += v;
                psq[c] += v * v;
            }
        }
    }
    if (stats) {
        __syncthreads();
        float* s_sum = sm;        // reuse smem
        float* s_sq = sm + 128;
        if (tid < 128) { s_sum[tid] = 0.f; s_sq[tid] = 0.f; }
        __syncthreads();
#pragma unroll
        for (int c = 0; c < 4; c++) {
            atomicAdd(&s_sum[lane + 32 * c], psum[c]);
            atomicAdd(&s_sq[lane + 32 * c], psq[c]);
        }
        __syncthreads();
        if (tid < 128) {
            atomicAdd(&stats[tid], s_sum[tid]);
            atomicAdd(&stats[128 + tid], s_sq[tid]);
        }
    }
}

// ---------------- BN stats finalize: stats -> (scale, shift) ----------------
__global__ void finalize_stats(float* stats, const float* __restrict__ gamma,
                               const float* __restrict__ beta, float invN) {
    int j = threadIdx.x;
    float s = stats[j], sq = stats[128 + j];
    float mu = s * invN;
    float var = fmaxf(sq * invN - mu * mu, 0.f);
    float rstd = rsqrtf(var + 1e-5f);
    float sc = rstd * gamma[j];
    stats[j] = sc;
    stats[128 + j] = beta[j] - mu * sc;
}

// ---------------- BN apply + residual: hout = hin + z*scale + shift ----------------
__global__ void bn_res_kernel(const float4* __restrict__ hin, const float4* __restrict__ z,
                              const float* __restrict__ ss, float4* __restrict__ hout, int n4) {
    int i = blockIdx.x * blockDim.x + threadIdx.x;
    int stride = gridDim.x * blockDim.x;
    for (; i < n4; i += stride) {
        int j4 = i & 31;
        float4 zv = z[i];
        float4 hv = hin[i];
        float4 sc = ((const float4*)ss)[j4];
        float4 sh = ((const float4*)(ss + 128))[j4];
        float4 o;
        o.x = hv.x + zv.x * sc.x + sh.x;
        o.y = hv.y + zv.y * sc.y + sh.y;
        o.z = hv.z + zv.z * sc.z + sh.z;
        o.w = hv.w + zv.w * sc.w + sh.w;
        hout[i] = o;
    }
}

// ---------------- context attention pooling -> qin[b][0:128] ----------------
__global__ void attn_kernel(const int* __restrict__ ctx_ids, const float* __restrict__ emb,
                            const float* __restrict__ attn_w, const float* __restrict__ attn_b,
                            float* __restrict__ qin) {
    __shared__ float s_ctx[CTX_LEN * D];
    __shared__ float s_aw[D];
    __shared__ float s_logit[64];
    __shared__ float s_wt[64];
    int b = blockIdx.x;
    int tid = threadIdx.x;          // 128 threads
    int lane = tid & 31, wid = tid >> 5;
    s_aw[tid] = attn_w[tid];
    for (int i = tid; i < CTX_LEN * D; i += 128) {
        int l = i >> 7, d = i & 127;
        int id = ctx_ids[b * CTX_LEN + l];
        s_ctx[i] = emb[(size_t)id * D + d];
    }
    __syncthreads();
    for (int l = wid; l < CTX_LEN; l += 4) {
        float p = 0.f;
#pragma unroll
        for (int c = 0; c < 4; c++)
            p += s_ctx[l * D + lane + 32 * c] * s_aw[lane + 32 * c];
#pragma unroll
        for (int off = 16; off; off >>= 1) p += __shfl_xor_sync(0xffffffffu, p, off);
        if (lane == 0) s_logit[l] = p + attn_b[0];
    }
    __syncthreads();
    if (wid == 0) {
        float x0 = (lane < CTX_LEN) ? s_logit[lane] : -1e30f;
        float x1 = (lane + 32 < CTX_LEN) ? s_logit[lane + 32] : -1e30f;
        float m = fmaxf(x0, x1);
#pragma unroll
        for (int off = 16; off; off >>= 1) m = fmaxf(m, __shfl_xor_sync(0xffffffffu, m, off));
        float e0 = (lane < CTX_LEN) ? expf(x0 - m) : 0.f;
        float e1 = (lane + 32 < CTX_LEN) ? expf(x1 - m) : 0.f;
        float s = e0 + e1;
#pragma unroll
        for (int off = 16; off; off >>= 1) s += __shfl_xor_sync(0xffffffffu, s, off);
        float inv = 1.f / s;
        if (lane < CTX_LEN) s_wt[lane] = e0 * inv;
        if (lane + 32 < CTX_LEN) s_wt[lane + 32] = e1 * inv;
    }
    __syncthreads();
    float acc = 0.f;
    for (int l = 0; l < CTX_LEN; l++) acc += s_wt[l] * s_ctx[l * D + tid];
    qin[b * 256 + tid] = acc;
}

// ---------------- build fusion input: [emb_table[miss] , masked graph gather] ----------------
__global__ void miss_in_kernel(const int* __restrict__ miss_ids, const int* __restrict__ v2fg,
                               const float* __restrict__ emb, const float* __restrict__ graph,
                               float* __restrict__ in256) {
    int idx = blockIdx.x * blockDim.x + threadIdx.x;
    int b = idx >> 7, d = idx & 127;
    if (b >= BATCH) return;
    int mid = miss_ids[b];
    in256[b * 256 + d] = emb[(size_t)mid * D + d];
    int fg = v2fg[mid];
    in256[b * 256 + 128 + d] = (fg >= 0) ? graph[(size_t)fg * D + d] : 0.f;
}

// ---------------- launch ----------------
extern "C" void kernel_launch(void* const* d_in, const int* in_sizes, int n_in,
                              void* d_out, int out_size) {
    const int*   edge_index = (const int*)d_in[0];
    const float* norm       = (const float*)d_in[1];
    const int*   ctx_ids    = (const int*)d_in[2];
    const int*   miss_ids   = (const int*)d_in[3];
    const int*   v2fg       = (const int*)d_in[4];
    const float* emb_table  = (const float*)d_in[5];
    const float* fg_emb     = (const float*)d_in[6];
    const float* gc_w       = (const float*)d_in[7];
    const float* bn_gamma   = (const float*)d_in[8];
    const float* bn_beta    = (const float*)d_in[9];
    const float* attn_w     = (const float*)d_in[10];
    const float* attn_b     = (const float*)d_in[11];
    const float* fusion_w   = (const float*)d_in[12];
    const float* fusion_b   = (const float*)d_in[13];
    const float* proj1_w    = (const float*)d_in[14];
    const float* proj1_b    = (const float*)d_in[15];
    const float* proj2_w    = (const float*)d_in[16];
    const float* proj2_b    = (const float*)d_in[17];

    float* out   = (float*)d_out;
    float* query = out;                       // [1024,128]
    float* graph = out + (size_t)BATCH * D;   // [50000,128]

    float *agg, *z, *h, *in256, *qin, *q1, *stats;
    cudaGetSymbolAddress((void**)&agg,   g_agg);
    cudaGetSymbolAddress((void**)&z,     g_z);
    cudaGetSymbolAddress((void**)&h,     g_h);
    cudaGetSymbolAddress((void**)&in256, g_in256);
    cudaGetSymbolAddress((void**)&qin,   g_qin);
    cudaGetSymbolAddress((void**)&q1,    g_q1);
    cudaGetSymbolAddress((void**)&stats, g_stats);

    cudaFuncSetAttribute(gemm_kernel, cudaFuncAttributeMaxDynamicSharedMemorySize, GEMM_SMEM);

    const int* rows = edge_index;
    const int* cols = edge_index + N_EDGES;
    const int total4 = N_NODES * (D / 4);     // 1.6M float4

    // batch-side attention (independent of graph path)
    attn_kernel<<<BATCH, 128>>>(ctx_ids, emb_table, attn_w, attn_b, qin);

    // GCN layers
    for (int l = 0; l < 2; l++) {
        const float* hin = (l == 0) ? fg_emb : h;
        zero_kernel<<<6250, 256>>>((float4*)agg, total4);
        scatter_kernel<<<4736, 256>>>(rows, cols, norm, hin, agg, N_EDGES);
        zero_kernel<<<1, 64>>>((float4*)stats, 64);
        gemm_kernel<<<dim3(782, 1), 256, GEMM_SMEM>>>(agg, gc_w + (size_t)l * D * D, nullptr, z,
                                                      N_NODES, D, D, D, 1, stats);
        finalize_stats<<<1, 128>>>(stats, bn_gamma + l * D, bn_beta + l * D, 1.0f / N_NODES);
        float* hout = (l == 0) ? h : graph;
        bn_res_kernel<<<6250, 256>>>((const float4*)hin, (const float4*)z, stats,
                                     (float4*)hout, total4);
    }

    // fusion + projection MLP
    miss_in_kernel<<<BATCH, 128>>>(miss_ids, v2fg, emb_table, graph, in256);
    gemm_kernel<<<dim3(16, 1), 256, GEMM_SMEM>>>(in256, fusion_w, fusion_b, qin + 128,
                                                 BATCH, 128, 256, 256, 0, nullptr);
    gemm_kernel<<<dim3(16, 2), 256, GEMM_SMEM>>>(qin, proj1_w, proj1_b, q1,
                                                 BATCH, 256, 256, 256, 1, nullptr);
    gemm_kernel<<<dim3(16, 1), 256, GEMM_SMEM>>>(q1, proj2_w, proj2_b, query,
                                                 BATCH, 128, 256, 128, 0, nullptr);
}

// round 5
// speedup vs baseline: 1.0950x; 1.0950x over previous
#include <cuda_runtime.h>
#include <cstdint>

#define N_NODES 50000
#define N_EDGES 800000
#define D 128
#define VOCAB 30000
#define BATCH 1024
#define CTX_LEN 50

// ---------------- scratch (no allocations allowed) ----------------
__device__ float g_agg[(size_t)N_NODES * D];
__device__ float g_z[(size_t)N_NODES * D];
__device__ float g_h[(size_t)N_NODES * D];
__device__ float g_in256[BATCH * 256];
__device__ float g_qin[BATCH * 256];
__device__ float g_q1[BATCH * 256];
__device__ float g_stats[512];           // 2 layers x (sum[128], sumsq[128])
__device__ int   g_deg[N_NODES];
__device__ int   g_offs[N_NODES + 1];
__device__ int   g_cursor[N_NODES];
__device__ int   g_ecol[N_EDGES];
__device__ float g_enorm[N_EDGES];

// ---------------- prep: zero degree counters + BN stats banks ----------------
__global__ void prep_kernel(int* __restrict__ deg, float* __restrict__ stats) {
    int i = blockIdx.x * blockDim.x + threadIdx.x;
    if (i < N_NODES) deg[i] = 0;
    if (i < 512) stats[i] = 0.f;
}

// ---------------- histogram of edge rows ----------------
__global__ void hist_kernel(const int* __restrict__ rows, int* __restrict__ deg) {
    int e = blockIdx.x * blockDim.x + threadIdx.x;
    if (e < N_EDGES) atomicAdd(&deg[rows[e]], 1);
}

// ---------------- exclusive scan of deg -> offs, cursor (single block) ----------------
__device__ __forceinline__ int warp_incl_scan(int v, int lane) {
#pragma unroll
    for (int o = 1; o < 32; o <<= 1) {
        int t = __shfl_up_sync(0xffffffffu, v, o);
        if (lane >= o) v += t;
    }
    return v;
}

__global__ void scan_kernel(const int* __restrict__ deg, int* __restrict__ offs,
                            int* __restrict__ cursor) {
    __shared__ int s_w[32];
    __shared__ int s_ws[32];
    __shared__ int s_carry;
    int tid = threadIdx.x;               // 1024 threads
    int lane = tid & 31, wid = tid >> 5;
    if (tid == 0) s_carry = 0;
    __syncthreads();
    for (int base = 0; base < N_NODES; base += 1024) {
        int i = base + tid;
        int v = (i < N_NODES) ? deg[i] : 0;
        int ws = warp_incl_scan(v, lane);
        if (lane == 31) s_w[wid] = ws;
        __syncthreads();
        if (wid == 0) {
            int t = s_w[lane];
            t = warp_incl_scan(t, lane);
            s_ws[lane] = t;
        }
        __syncthreads();
        int incl = ws + (wid ? s_ws[wid - 1] : 0);
        int excl = s_carry + incl - v;
        if (i < N_NODES) { offs[i] = excl; cursor[i] = excl; }
        __syncthreads();
        if (tid == 0) s_carry += s_ws[31];
        __syncthreads();
    }
    if (tid == 0) offs[N_NODES] = s_carry;   // == N_EDGES
}

// ---------------- counting-sort permute: edge (col, norm) grouped by row ----------------
__global__ void permute_kernel(const int* __restrict__ rows, const int* __restrict__ cols,
                               const float* __restrict__ norm, int* __restrict__ cursor,
                               int* __restrict__ ecol, float* __restrict__ enorm) {
    int e = blockIdx.x * blockDim.x + threadIdx.x;
    if (e >= N_EDGES) return;
    int r = rows[e];
    int pos = atomicAdd(&cursor[r], 1);
    ecol[pos] = cols[e];
    enorm[pos] = norm[e];
}

// ---------------- CSR gather: agg[i] = sum_e norm_e * h[col_e]  (no atomics) ----------
// warp per node; lane owns one float4 of the 128-wide row; 4-wide edge unroll for MLP.
__global__ void gather_kernel(const int* __restrict__ offs, const int* __restrict__ ecol,
                              const float* __restrict__ enorm, const float* __restrict__ h,
                              float* __restrict__ agg) {
    int warp = blockIdx.x * (blockDim.x >> 5) + (threadIdx.x >> 5);
    if (warp >= N_NODES) return;
    int lane = threadIdx.x & 31;
    int e = offs[warp], end = offs[warp + 1];
    float4 a0 = make_float4(0.f, 0.f, 0.f, 0.f);
    float4 a1 = make_float4(0.f, 0.f, 0.f, 0.f);
    float4 a2 = make_float4(0.f, 0.f, 0.f, 0.f);
    float4 a3 = make_float4(0.f, 0.f, 0.f, 0.f);
    for (; e + 3 < end; e += 4) {
        int c0 = ecol[e],     c1 = ecol[e + 1];
        int c2 = ecol[e + 2], c3 = ecol[e + 3];
        float w0 = enorm[e],     w1 = enorm[e + 1];
        float w2 = enorm[e + 2], w3 = enorm[e + 3];
        float4 v0 = *((const float4*)(h + (size_t)c0 * D) + lane);
        float4 v1 = *((const float4*)(h + (size_t)c1 * D) + lane);
        float4 v2 = *((const float4*)(h + (size_t)c2 * D) + lane);
        float4 v3 = *((const float4*)(h + (size_t)c3 * D) + lane);
        a0.x = fmaf(w0, v0.x, a0.x); a0.y = fmaf(w0, v0.y, a0.y);
        a0.z = fmaf(w0, v0.z, a0.z); a0.w = fmaf(w0, v0.w, a0.w);
        a1.x = fmaf(w1, v1.x, a1.x); a1.y = fmaf(w1, v1.y, a1.y);
        a1.z = fmaf(w1, v1.z, a1.z); a1.w = fmaf(w1, v1.w, a1.w);
        a2.x = fmaf(w2, v2.x, a2.x); a2.y = fmaf(w2, v2.y, a2.y);
        a2.z = fmaf(w2, v2.z, a2.z); a2.w = fmaf(w2, v2.w, a2.w);
        a3.x = fmaf(w3, v3.x, a3.x); a3.y = fmaf(w3, v3.y, a3.y);
        a3.z = fmaf(w3, v3.z, a3.z); a3.w = fmaf(w3, v3.w, a3.w);
    }
    for (; e < end; e++) {
        int c0 = ecol[e];
        float w0 = enorm[e];
        float4 v0 = *((const float4*)(h + (size_t)c0 * D) + lane);
        a0.x = fmaf(w0, v0.x, a0.x); a0.y = fmaf(w0, v0.y, a0.y);
        a0.z = fmaf(w0, v0.z, a0.z); a0.w = fmaf(w0, v0.w, a0.w);
    }
    a0.x += a1.x; a0.y += a1.y; a0.z += a1.z; a0.w += a1.w;
    a2.x += a3.x; a2.y += a3.y; a2.z += a3.z; a2.w += a3.w;
    a0.x += a2.x; a0.y += a2.y; a0.z += a2.z; a0.w += a2.w;
    *((float4*)(agg + (size_t)warp * D) + lane) = a0;
}

// ---------------- generic GEMM: out[M,N] = act(A[M,K] @ W[N,K]^T + bias) ----------------
#define SBK 129
#define GEMM_SMEM ((64 * 128 + 128 * SBK) * 4)

__global__ void __launch_bounds__(256, 2)
gemm_kernel(const float* __restrict__ A, const float* __restrict__ W,
            const float* __restrict__ bias, float* __restrict__ out,
            int M, int N, int K, int ldout, int do_relu, float* __restrict__ stats) {
    extern __shared__ float sm[];
    float* sA = sm;              // [64][128]
    float* sB = sm + 64 * 128;   // [128][SBK]
    int tid = threadIdx.x;
    int lane = tid & 31, wid = tid >> 5;
    int bm = blockIdx.x * 64;
    int bn = blockIdx.y * 128;

    float acc[8][4];
#pragma unroll
    for (int i = 0; i < 8; i++)
#pragma unroll
        for (int c = 0; c < 4; c++) acc[i][c] = 0.f;

    int rg = wid * 8;
    for (int k0 = 0; k0 < K; k0 += 128) {
        __syncthreads();
        for (int i = tid; i < 64 * 32; i += 256) {
            int r = i >> 5, c4 = i & 31;
            int gr = bm + r;
            float4 v = make_float4(0.f, 0.f, 0.f, 0.f);
            if (gr < M) v = *(const float4*)(A + (size_t)gr * K + k0 + c4 * 4);
            *(float4*)(sA + r * 128 + c4 * 4) = v;
        }
        for (int i = tid; i < 128 * 32; i += 256) {
            int n = i >> 5, k4 = i & 31;
            float4 v = *(const float4*)(W + (size_t)(bn + n) * K + k0 + k4 * 4);
            float* p = sB + n * SBK + k4 * 4;
            p[0] = v.x; p[1] = v.y; p[2] = v.z; p[3] = v.w;
        }
        __syncthreads();
#pragma unroll 4
        for (int k = 0; k < 128; k++) {
            float b0 = sB[(lane)      * SBK + k];
            float b1 = sB[(lane + 32) * SBK + k];
            float b2 = sB[(lane + 64) * SBK + k];
            float b3 = sB[(lane + 96) * SBK + k];
#pragma unroll
            for (int i = 0; i < 8; i++) {
                float a = sA[(rg + i) * 128 + k];
                acc[i][0] = fmaf(a, b0, acc[i][0]);
                acc[i][1] = fmaf(a, b1, acc[i][1]);
                acc[i][2] = fmaf(a, b2, acc[i][2]);
                acc[i][3] = fmaf(a, b3, acc[i][3]);
            }
        }
    }

    float bv[4];
#pragma unroll
    for (int c = 0; c < 4; c++) bv[c] = bias ? bias[bn + lane + 32 * c] : 0.f;
    float psum[4] = {0.f, 0.f, 0.f, 0.f}, psq[4] = {0.f, 0.f, 0.f, 0.f};
#pragma unroll
    for (int i = 0; i < 8; i++) {
        int gr = bm + rg + i;
        if (gr < M) {
#pragma unroll
            for (int c = 0; c < 4; c++) {
                float v = acc[i][c] + bv[c];
                if (do_relu) v = fmaxf(v, 0.f);
                out[(size_t)gr * ldout + bn + lane + 32 * c] = v;
                psum[c] += v;
                psq[c] += v * v;
            }
        }
    }
    if (stats) {
        __syncthreads();
        float* s_sum = sm;
        float* s_sq = sm + 128;
        if (tid < 128) { s_sum[tid] = 0.f; s_sq[tid] = 0.f; }
        __syncthreads();
#pragma unroll
        for (int c = 0; c < 4; c++) {
            atomicAdd(&s_sum[lane + 32 * c], psum[c]);
            atomicAdd(&s_sq[lane + 32 * c], psq[c]);
        }
        __syncthreads();
        if (tid < 128) {
            atomicAdd(&stats[tid], s_sum[tid]);
            atomicAdd(&stats[128 + tid], s_sq[tid]);
        }
    }
}

// ---------------- BN stats finalize ----------------
__global__ void finalize_stats(float* stats, const float* __restrict__ gamma,
                               const float* __restrict__ beta, float invN) {
    int j = threadIdx.x;
    float s = stats[j], sq = stats[128 + j];
    float mu = s * invN;
    float var = fmaxf(sq * invN - mu * mu, 0.f);
    float rstd = rsqrtf(var + 1e-5f);
    float sc = rstd * gamma[j];
    stats[j] = sc;
    stats[128 + j] = beta[j] - mu * sc;
}

// ---------------- BN apply + residual ----------------
__global__ void bn_res_kernel(const float4* __restrict__ hin, const float4* __restrict__ z,
                              const float* __restrict__ ss, float4* __restrict__ hout, int n4) {
    int i = blockIdx.x * blockDim.x + threadIdx.x;
    int stride = gridDim.x * blockDim.x;
    for (; i < n4; i += stride) {
        int j4 = i & 31;
        float4 zv = z[i];
        float4 hv = hin[i];
        float4 sc = ((const float4*)ss)[j4];
        float4 sh = ((const float4*)(ss + 128))[j4];
        float4 o;
        o.x = hv.x + zv.x * sc.x + sh.x;
        o.y = hv.y + zv.y * sc.y + sh.y;
        o.z = hv.z + zv.z * sc.z + sh.z;
        o.w = hv.w + zv.w * sc.w + sh.w;
        hout[i] = o;
    }
}

// ---------------- context attention pooling -> qin[b][0:128] ----------------
__global__ void attn_kernel(const int* __restrict__ ctx_ids, const float* __restrict__ emb,
                            const float* __restrict__ attn_w, const float* __restrict__ attn_b,
                            float* __restrict__ qin) {
    __shared__ float s_ctx[CTX_LEN * D];
    __shared__ float s_aw[D];
    __shared__ float s_logit[64];
    __shared__ float s_wt[64];
    int b = blockIdx.x;
    int tid = threadIdx.x;          // 128 threads
    int lane = tid & 31, wid = tid >> 5;
    s_aw[tid] = attn_w[tid];
    for (int i = tid; i < CTX_LEN * D; i += 128) {
        int l = i >> 7, d = i & 127;
        int id = ctx_ids[b * CTX_LEN + l];
        s_ctx[i] = emb[(size_t)id * D + d];
    }
    __syncthreads();
    for (int l = wid; l < CTX_LEN; l += 4) {
        float p = 0.f;
#pragma unroll
        for (int c = 0; c < 4; c++)
            p += s_ctx[l * D + lane + 32 * c] * s_aw[lane + 32 * c];
#pragma unroll
        for (int off = 16; off; off >>= 1) p += __shfl_xor_sync(0xffffffffu, p, off);
        if (lane == 0) s_logit[l] = p + attn_b[0];
    }
    __syncthreads();
    if (wid == 0) {
        float x0 = (lane < CTX_LEN) ? s_logit[lane] : -1e30f;
        float x1 = (lane + 32 < CTX_LEN) ? s_logit[lane + 32] : -1e30f;
        float m = fmaxf(x0, x1);
#pragma unroll
        for (int off = 16; off; off >>= 1) m = fmaxf(m, __shfl_xor_sync(0xffffffffu, m, off));
        float e0 = (lane < CTX_LEN) ? expf(x0 - m) : 0.f;
        float e1 = (lane + 32 < CTX_LEN) ? expf(x1 - m) : 0.f;
        float s = e0 + e1;
#pragma unroll
        for (int off = 16; off; off >>= 1) s += __shfl_xor_sync(0xffffffffu, s, off);
        float inv = 1.f / s;
        if (lane < CTX_LEN) s_wt[lane] = e0 * inv;
        if (lane + 32 < CTX_LEN) s_wt[lane + 32] = e1 * inv;
    }
    __syncthreads();
    float acc = 0.f;
    for (int l = 0; l < CTX_LEN; l++) acc += s_wt[l] * s_ctx[l * D + tid];
    qin[b * 256 + tid] = acc;
}

// ---------------- build fusion input ----------------
__global__ void miss_in_kernel(const int* __restrict__ miss_ids, const int* __restrict__ v2fg,
                               const float* __restrict__ emb, const float* __restrict__ graph,
                               float* __restrict__ in256) {
    int idx = blockIdx.x * blockDim.x + threadIdx.x;
    int b = idx >> 7, d = idx & 127;
    if (b >= BATCH) return;
    int mid = miss_ids[b];
    in256[b * 256 + d] = emb[(size_t)mid * D + d];
    int fg = v2fg[mid];
    in256[b * 256 + 128 + d] = (fg >= 0) ? graph[(size_t)fg * D + d] : 0.f;
}

// ---------------- launch ----------------
extern "C" void kernel_launch(void* const* d_in, const int* in_sizes, int n_in,
                              void* d_out, int out_size) {
    const int*   edge_index = (const int*)d_in[0];
    const float* norm       = (const float*)d_in[1];
    const int*   ctx_ids    = (const int*)d_in[2];
    const int*   miss_ids   = (const int*)d_in[3];
    const int*   v2fg       = (const int*)d_in[4];
    const float* emb_table  = (const float*)d_in[5];
    const float* fg_emb     = (const float*)d_in[6];
    const float* gc_w       = (const float*)d_in[7];
    const float* bn_gamma   = (const float*)d_in[8];
    const float* bn_beta    = (const float*)d_in[9];
    const float* attn_w     = (const float*)d_in[10];
    const float* attn_b     = (const float*)d_in[11];
    const float* fusion_w   = (const float*)d_in[12];
    const float* fusion_b   = (const float*)d_in[13];
    const float* proj1_w    = (const float*)d_in[14];
    const float* proj1_b    = (const float*)d_in[15];
    const float* proj2_w    = (const float*)d_in[16];
    const float* proj2_b    = (const float*)d_in[17];

    float* out   = (float*)d_out;
    float* query = out;                       // [1024,128]
    float* graph = out + (size_t)BATCH * D;   // [50000,128]

    float *agg, *z, *h, *in256, *qin, *q1, *stats, *enorm;
    int *deg, *offs, *cursor, *ecol;
    cudaGetSymbolAddress((void**)&agg,    g_agg);
    cudaGetSymbolAddress((void**)&z,      g_z);
    cudaGetSymbolAddress((void**)&h,      g_h);
    cudaGetSymbolAddress((void**)&in256,  g_in256);
    cudaGetSymbolAddress((void**)&qin,    g_qin);
    cudaGetSymbolAddress((void**)&q1,     g_q1);
    cudaGetSymbolAddress((void**)&stats,  g_stats);
    cudaGetSymbolAddress((void**)&deg,    g_deg);
    cudaGetSymbolAddress((void**)&offs,   g_offs);
    cudaGetSymbolAddress((void**)&cursor, g_cursor);
    cudaGetSymbolAddress((void**)&ecol,   g_ecol);
    cudaGetSymbolAddress((void**)&enorm,  g_enorm);

    cudaFuncSetAttribute(gemm_kernel, cudaFuncAttributeMaxDynamicSharedMemorySize, GEMM_SMEM);

    const int* rows = edge_index;
    const int* cols = edge_index + N_EDGES;
    const int total4 = N_NODES * (D / 4);     // 1.6M float4

    // CSR build (once per call; shared by both layers)
    prep_kernel<<<196, 256>>>(deg, stats);
    hist_kernel<<<3125, 256>>>(rows, deg);
    scan_kernel<<<1, 1024>>>(deg, offs, cursor);
    permute_kernel<<<3125, 256>>>(rows, cols, norm, cursor, ecol, enorm);

    // batch-side attention (independent of graph path)
    attn_kernel<<<BATCH, 128>>>(ctx_ids, emb_table, attn_w, attn_b, qin);

    // GCN layers
    for (int l = 0; l < 2; l++) {
        const float* hin = (l == 0) ? fg_emb : h;
        float* lstats = stats + l * 256;
        gather_kernel<<<6250, 256>>>(offs, ecol, enorm, hin, agg);
        gemm_kernel<<<dim3(782, 1), 256, GEMM_SMEM>>>(agg, gc_w + (size_t)l * D * D, nullptr, z,
                                                      N_NODES, D, D, D, 1, lstats);
        finalize_stats<<<1, 128>>>(lstats, bn_gamma + l * D, bn_beta + l * D, 1.0f / N_NODES);
        float* hout = (l == 0) ? h : graph;
        bn_res_kernel<<<6250, 256>>>((const float4*)hin, (const float4*)z, lstats,
                                     (float4*)hout, total4);
    }

    // fusion + projection MLP
    miss_in_kernel<<<BATCH, 128>>>(miss_ids, v2fg, emb_table, graph, in256);
    gemm_kernel<<<dim3(16, 1), 256, GEMM_SMEM>>>(in256, fusion_w, fusion_b, qin + 128,
                                                 BATCH, 128, 256, 256, 0, nullptr);
    gemm_kernel<<<dim3(16, 2), 256, GEMM_SMEM>>>(qin, proj1_w, proj1_b, q1,
                                                 BATCH, 256, 256, 256, 1, nullptr);
    gemm_kernel<<<dim3(16, 1), 256, GEMM_SMEM>>>(q1, proj2_w, proj2_b, query,
                                                 BATCH, 128, 256, 128, 0, nullptr);
}